// round 16
// baseline (speedup 1.0000x reference)
#include <cuda_runtime.h>
#include <cuda_fp16.h>
#include <cstdint>
#include <math.h>

// Problem constants
#define BDIM 4
#define TDIM 4096
#define CDIM 1024
#define HDIM 2048
#define MTOT (BDIM * TDIM)   // 16384
#define NCH  32              // cumsum chunks
#define CLEN (TDIM / NCH)    // 128

// Scratch (device globals: allocation-free per harness rules)
__device__ float  g_s [(size_t)MTOT * HDIM];        // silu branch (fp32)
__device__ __half g_hh[(size_t)MTOT * 2 * HDIM];    // agg branch (fp16)
__device__ __half g_sh[(size_t)MTOT * HDIM];        // gated s*agg (fp16, GEMM3 A)
__device__ __half g_xh[(size_t)MTOT * CDIM];        // x fp16
__device__ __half g_wsh[(size_t)HDIM * CDIM];       // W_sel^T fp16 [N,K]
__device__ __half g_wah[(size_t)2 * HDIM * CDIM];   // W_agg^T fp16 [N,K]
__device__ __half g_woh[(size_t)CDIM * HDIM];       // W_out^T fp16 [N,K]
__device__ float  g_part[BDIM * NCH * HDIM];        // cumsum partials

// ---------------------------------------------------------------------------
// PTX helpers (plain sm_80-era features only: compile under compute_103)
// ---------------------------------------------------------------------------
__device__ __forceinline__ void cpasync16(uint32_t saddr, const void* g) {
    asm volatile("cp.async.cg.shared.global [%0], [%1], 16;" :: "r"(saddr), "l"(g));
}
__device__ __forceinline__ void ldsm4(uint32_t* r, uint32_t saddr) {
    asm volatile("ldmatrix.sync.aligned.m8n8.x4.shared.b16 {%0,%1,%2,%3}, [%4];"
                 : "=r"(r[0]), "=r"(r[1]), "=r"(r[2]), "=r"(r[3]) : "r"(saddr));
}
__device__ __forceinline__ void mma_f16(float* c, const uint32_t* a,
                                        uint32_t b0, uint32_t b1) {
    asm volatile(
        "mma.sync.aligned.m16n8k16.row.col.f32.f16.f16.f32 "
        "{%0,%1,%2,%3}, {%4,%5,%6,%7}, {%8,%9}, {%0,%1,%2,%3};"
        : "+f"(c[0]), "+f"(c[1]), "+f"(c[2]), "+f"(c[3])
        : "r"(a[0]), "r"(a[1]), "r"(a[2]), "r"(a[3]), "r"(b0), "r"(b1));
}

// ---------------------------------------------------------------------------
// fp16 tensor-core GEMM: C[M,N] = A[M,K](fp16) @ Wt[N,K](fp16)^T.
// BMT x 128 CTA tile (256 thr, 8 warps 2x4), BK=64 halves, 3-stage ring,
// multistage schedule, one barrier per k-tile, 2 CTAs/SM.
//   BMT=128: warp tile 64x32 (round-12 engine).
//   BMT=64 : warp tile 32x32 (fine tiles for GEMM3 -> 6.9 waves, tiny tail).
// EPI: 0 = y*scale[n] ; 1 = silu(y*scale[n]) ; 2 = plain.  TO: float | __half
// ---------------------------------------------------------------------------
constexpr int BN = 128, BKH = 64;
constexpr int KPAD = 72;                       // halves per padded row
constexpr int ROWB = KPAD * 2;                 // 144 bytes per row
constexpr int STAGES = 3;
constexpr int smem_bytes(int bmt) { return STAGES * (bmt + BN) * ROWB; }

template <int EPI, typename TO, int BMT>
__global__ __launch_bounds__(256, 2)
void hgemm(const __half* __restrict__ A, const __half* __restrict__ Wt,
           TO* __restrict__ C, const float* __restrict__ scale,
           int M, int N, int K)
{
    constexpr int MI = BMT / 32;               // m-frag count per warp (4 or 2)
    constexpr int ATILE_B = BMT * ROWB;
    constexpr int BTILE_B = BN * ROWB;
    constexpr int STAGE_B = ATILE_B + BTILE_B;

    extern __shared__ __half sm[];
    const uint32_t smb = (uint32_t)__cvta_generic_to_shared(sm);

    const int tid  = threadIdx.x;
    const int lane = tid & 31;
    const int wid  = tid >> 5;
    const int wm   = (wid >> 2) * (16 * MI);   // warp m offset
    const int wn   = (wid & 3) * 32;           // warp n offset
    const int bm   = blockIdx.y * BMT;
    const int bn   = blockIdx.x * BN;
    const int nt   = K / BKH;

    // A ldmatrix.x4 lane offset: row = lane%16, kcol = (lane/16)*8 halves
    const uint32_t a_lane = (uint32_t)((lane & 15) * ROWB + (lane >> 4) * 16);
    // B ldmatrix.x4 lane offset
    const int bg = lane >> 3, br = lane & 7;
    const uint32_t b_lane = (uint32_t)(((bg >> 1) * 8 + br) * ROWB + (bg & 1) * 16);

    auto issue_tile = [&](int t, int s) {
        const int k0 = t * BKH;
        const uint32_t ab = smb + (uint32_t)s * STAGE_B;
        const uint32_t bb = ab + ATILE_B;
#pragma unroll
        for (int i = 0; i < MI; ++i) {         // A: BMT*8 chunks / 256 thr
            int idx = tid + (i << 8);
            int r = idx >> 3, c = idx & 7;
            cpasync16(ab + (uint32_t)(r * ROWB + c * 16),
                      A + (size_t)(bm + r) * K + k0 + c * 8);
        }
#pragma unroll
        for (int i = 0; i < 4; ++i) {          // B: 128*8 chunks / 256 thr
            int idx = tid + (i << 8);
            int r = idx >> 3, c = idx & 7;
            cpasync16(bb + (uint32_t)(r * ROWB + c * 16),
                      Wt + (size_t)(bn + r) * K + k0 + c * 8);
        }
    };

    // Prologue: tiles 0 and 1 in flight; wait for tile 0.
    issue_tile(0, 0);
    asm volatile("cp.async.commit_group;");
    issue_tile(1, 1);
    asm volatile("cp.async.commit_group;");
    asm volatile("cp.async.wait_group 1;");
    __syncthreads();

    float acc[MI][4][4];
#pragma unroll
    for (int i = 0; i < MI; ++i)
#pragma unroll
        for (int j = 0; j < 4; ++j)
#pragma unroll
            for (int q = 0; q < 4; ++q) acc[i][j][q] = 0.f;

    for (int t = 0; t < nt; ++t) {
        const int buf = t % STAGES;
        if (t + 2 < nt) issue_tile(t + 2, (t + 2) % STAGES);
        asm volatile("cp.async.commit_group;");

        const uint32_t ab = smb + (uint32_t)buf * STAGE_B;
        const uint32_t bb = ab + ATILE_B;
#pragma unroll
        for (int ks = 0; ks < 4; ++ks) {       // 4 x k16
            uint32_t af[MI][4];
#pragma unroll
            for (int i = 0; i < MI; ++i)
                ldsm4(af[i], ab + (uint32_t)((wm + i * 16) * ROWB + ks * 32) + a_lane);
            uint32_t bf[2][4];
#pragma unroll
            for (int jj = 0; jj < 2; ++jj)
                ldsm4(bf[jj], bb + (uint32_t)((wn + jj * 16) * ROWB + ks * 32) + b_lane);
#pragma unroll
            for (int i = 0; i < MI; ++i) {
#pragma unroll
                for (int jj = 0; jj < 2; ++jj) {
                    mma_f16(acc[i][2 * jj],     af[i], bf[jj][0], bf[jj][1]);
                    mma_f16(acc[i][2 * jj + 1], af[i], bf[jj][2], bf[jj][3]);
                }
            }
        }

        asm volatile("cp.async.wait_group 1;");
        __syncthreads();
    }

    // Epilogue: direct fragment stores
    const int qr = lane >> 2;              // 0..7
    const int qc = (lane & 3) << 1;        // 0,2,4,6
#pragma unroll
    for (int i = 0; i < MI; ++i) {
        const int m0 = bm + wm + i * 16 + qr;
#pragma unroll
        for (int j = 0; j < 4; ++j) {
            const int n0 = bn + wn + j * 8 + qc;
            float v0 = acc[i][j][0], v1 = acc[i][j][1];
            float v2 = acc[i][j][2], v3 = acc[i][j][3];
            if (EPI == 0 || EPI == 1) {
                float s0 = scale[n0], s1 = scale[n0 + 1];
                v0 *= s0; v1 *= s1; v2 *= s0; v3 *= s1;
            }
            if (EPI == 1) {
                v0 = v0 / (1.f + __expf(-v0));
                v1 = v1 / (1.f + __expf(-v1));
                v2 = v2 / (1.f + __expf(-v2));
                v3 = v3 / (1.f + __expf(-v3));
            }
            if (sizeof(TO) == 2) {   // fp16 output: packed 4B stores
                __half2 p0 = __floats2half2_rn(v0, v1);
                __half2 p1 = __floats2half2_rn(v2, v3);
                *(__half2*)((__half*)C + (size_t)m0 * N + n0)       = p0;
                *(__half2*)((__half*)C + (size_t)(m0 + 8) * N + n0) = p1;
            } else {
                *(float2*)((float*)C + (size_t)m0 * N + n0)       = make_float2(v0, v1);
                *(float2*)((float*)C + (size_t)(m0 + 8) * N + n0) = make_float2(v2, v3);
            }
        }
    }
}

// ---------------------------------------------------------------------------
// Preprocessing: fp32 -> fp16 convert; all three weight transposes fused into
// one launch (flat tile index -> matrix select).
// ---------------------------------------------------------------------------
__global__ void cvt_half(const float4* __restrict__ in, __half2* __restrict__ out,
                         int n4)
{
    int i = blockIdx.x * blockDim.x + threadIdx.x;
    if (i < n4) {
        float4 v = in[i];
        out[2 * i]     = __floats2half2_rn(v.x, v.y);
        out[2 * i + 1] = __floats2half2_rn(v.z, v.w);
    }
}

// tiles: sel (N=HDIM,K=CDIM) 2048 | agg (N=2*HDIM,K=CDIM) 4096 | out (N=CDIM,K=HDIM) 2048
constexpr int TSEL = (HDIM / 32) * (CDIM / 32);        // 2048
constexpr int TAGG = (2 * HDIM / 32) * (CDIM / 32);    // 4096
constexpr int TOUT = (CDIM / 32) * (HDIM / 32);        // 2048
__global__ void transpose_all(const float* __restrict__ Wsel,
                              const float* __restrict__ Wagg,
                              const float* __restrict__ Wout,
                              __half* __restrict__ wsh,
                              __half* __restrict__ wah,
                              __half* __restrict__ woh)
{
    __shared__ float t[32][33];
    int bidx = blockIdx.x;
    const float* in; __half* out; int K, N;
    if (bidx < TSEL)              { in = Wsel; out = wsh; K = CDIM; N = HDIM; }
    else if (bidx < TSEL + TAGG)  { in = Wagg; out = wah; K = CDIM; N = 2 * HDIM; bidx -= TSEL; }
    else                          { in = Wout; out = woh; K = HDIM; N = CDIM; bidx -= TSEL + TAGG; }
    const int n0 = (bidx % (N / 32)) * 32;
    const int k0 = (bidx / (N / 32)) * 32;
    const int x = threadIdx.x, y = threadIdx.y;
#pragma unroll
    for (int j = 0; j < 32; j += 8)
        t[y + j][x] = in[(size_t)(k0 + y + j) * N + n0 + x];
    __syncthreads();
#pragma unroll
    for (int j = 0; j < 32; j += 8)
        out[(size_t)(n0 + y + j) * K + k0 + x] = __float2half_rn(t[x][y + j]);
}

// ---------------------------------------------------------------------------
// Cumsum (2-phase, half2-vectorized): poly = c0 + c0*c1.
// Phase 1: per-chunk partial sums. Phase 2: scan + causal mean + gate
//   sh = half(s * acc/(t+1))   (fp16 input for GEMM3)
// ---------------------------------------------------------------------------
__global__ void poly_partial(const __half2* __restrict__ h2,
                             float2* __restrict__ part2)
{
    const int ch2 = blockIdx.x * blockDim.x + threadIdx.x;   // 0..HDIM/2-1
    const int c  = blockIdx.y, b = blockIdx.z;
    const __half2* hp = h2 + ((size_t)b * TDIM + (size_t)c * CLEN) * HDIM + ch2;
    float2 acc = make_float2(0.f, 0.f);
#pragma unroll 4
    for (int t = 0; t < CLEN; ++t) {
        float2 c0 = __half22float2(hp[(size_t)t * HDIM]);
        float2 c1 = __half22float2(hp[(size_t)t * HDIM + HDIM / 2]);
        acc.x += fmaf(c0.x, c1.x, c0.x);
        acc.y += fmaf(c0.y, c1.y, c0.y);
    }
    part2[((size_t)b * NCH + c) * (HDIM / 2) + ch2] = acc;
}
__global__ void poly_scan_gate(const __half2* __restrict__ h2,
                               const float2* __restrict__ part2,
                               const float2* __restrict__ s2,
                               __half2* __restrict__ sh2)
{
    const int ch2 = blockIdx.x * blockDim.x + threadIdx.x;
    const int c  = blockIdx.y, b = blockIdx.z;
    float2 acc = make_float2(0.f, 0.f);
    for (int c2 = 0; c2 < c; ++c2) {
        float2 p = part2[((size_t)b * NCH + c2) * (HDIM / 2) + ch2];
        acc.x += p.x; acc.y += p.y;
    }
    const __half2* hp = h2 + ((size_t)b * TDIM + (size_t)c * CLEN) * HDIM + ch2;
    const float2* sp = s2 + ((size_t)b * TDIM + (size_t)c * CLEN) * (HDIM / 2) + ch2;
    __half2* op = sh2 + ((size_t)b * TDIM + (size_t)c * CLEN) * (HDIM / 2) + ch2;
    const int t0 = c * CLEN;
#pragma unroll 4
    for (int t = 0; t < CLEN; ++t) {
        float2 c0 = __half22float2(hp[(size_t)t * HDIM]);
        float2 c1 = __half22float2(hp[(size_t)t * HDIM + HDIM / 2]);
        acc.x += fmaf(c0.x, c1.x, c0.x);
        acc.y += fmaf(c0.y, c1.y, c0.y);
        float inv = 1.0f / (float)(t0 + t + 1);
        float2 sv = sp[(size_t)t * (HDIM / 2)];
        op[(size_t)t * (HDIM / 2)] =
            __floats2half2_rn(sv.x * acc.x * inv, sv.y * acc.y * inv);
    }
}

// ---------------------------------------------------------------------------
// Launch
// ---------------------------------------------------------------------------
extern "C" void kernel_launch(void* const* d_in, const int* in_sizes, int n_in,
                              void* d_out, int out_size)
{
    const float* x     = (const float*)d_in[0];
    const float* W_sel = (const float*)d_in[1];
    const float* W_agg = (const float*)d_in[2];
    const float* W_out = (const float*)d_in[3];
    const float* sqk_q = (const float*)d_in[4];
    const float* sqk_k = (const float*)d_in[5];
    float* out = (float*)d_out;

    float *s_p, *part;
    __half *hh, *sh, *xh, *wsh, *wah, *woh;
    cudaGetSymbolAddress((void**)&s_p, g_s);
    cudaGetSymbolAddress((void**)&hh, g_hh);
    cudaGetSymbolAddress((void**)&sh, g_sh);
    cudaGetSymbolAddress((void**)&xh, g_xh);
    cudaGetSymbolAddress((void**)&wsh, g_wsh);
    cudaGetSymbolAddress((void**)&wah, g_wah);
    cudaGetSymbolAddress((void**)&woh, g_woh);
    cudaGetSymbolAddress((void**)&part, g_part);

    cudaFuncSetAttribute((const void*)hgemm<1, float, 128>,
                         cudaFuncAttributeMaxDynamicSharedMemorySize, smem_bytes(128));
    cudaFuncSetAttribute((const void*)hgemm<0, __half, 128>,
                         cudaFuncAttributeMaxDynamicSharedMemorySize, smem_bytes(128));
    cudaFuncSetAttribute((const void*)hgemm<2, float, 64>,
                         cudaFuncAttributeMaxDynamicSharedMemorySize, smem_bytes(64));

    // Preprocess: x -> fp16 ; weights -> transposed fp16 [N,K] (one launch)
    {
        int n4 = MTOT * CDIM / 4;
        cvt_half<<<(n4 + 255) / 256, 256>>>((const float4*)x, (__half2*)xh, n4);
        transpose_all<<<TSEL + TAGG + TOUT, dim3(32, 8)>>>(
            W_sel, W_agg, W_out, wsh, wah, woh);
    }

    dim3 blk(256);
    // s = silu((x @ W_sel) * sqk_q)            [16384 x 2048, K=1024] -> fp32
    hgemm<1, float, 128><<<dim3(HDIM / BN, MTOT / 128), blk, smem_bytes(128)>>>(
        xh, wsh, s_p, sqk_q, MTOT, HDIM, CDIM);
    // h = (x @ W_agg) * sqk_k                  [16384 x 4096, K=1024] -> fp16
    hgemm<0, __half, 128><<<dim3(2 * HDIM / BN, MTOT / 128), blk, smem_bytes(128)>>>(
        xh, wah, hh, sqk_k, MTOT, 2 * HDIM, CDIM);
    // poly -> causal running mean -> gate      (fp32 math, fp16 out)
    poly_partial<<<dim3(HDIM / 2 / 256, NCH, BDIM), 256>>>(
        (const __half2*)hh, (float2*)part);
    poly_scan_gate<<<dim3(HDIM / 2 / 256, NCH, BDIM), 256>>>(
        (const __half2*)hh, (const float2*)part, (const float2*)s_p, (__half2*)sh);
    // out = (s*agg) @ W_out  [16384 x 1024, K=2048] -> fp32, fine 64-row tiles
    hgemm<2, float, 64><<<dim3(CDIM / BN, MTOT / 64), blk, smem_bytes(64)>>>(
        sh, woh, out, nullptr, MTOT, CDIM, HDIM);
}

// round 17
// speedup vs baseline: 1.0116x; 1.0116x over previous
#include <cuda_runtime.h>
#include <cuda_fp16.h>
#include <cstdint>
#include <math.h>

// Problem constants
#define BDIM 4
#define TDIM 4096
#define CDIM 1024
#define HDIM 2048
#define MTOT (BDIM * TDIM)   // 16384
#define NCH  32              // cumsum chunks
#define CLEN (TDIM / NCH)    // 128

// Scratch (device globals: allocation-free per harness rules)
__device__ float  g_s [(size_t)MTOT * HDIM];        // silu branch (fp32)
__device__ __half g_hh[(size_t)MTOT * 2 * HDIM];    // agg branch (fp16)
__device__ __half g_sh[(size_t)MTOT * HDIM];        // gated s*agg (fp16, GEMM3 A)
__device__ __half g_xh[(size_t)MTOT * CDIM];        // x fp16
__device__ __half g_wsh[(size_t)HDIM * CDIM];       // W_sel^T fp16 [N,K]
__device__ __half g_wah[(size_t)2 * HDIM * CDIM];   // W_agg^T fp16 [N,K]
__device__ __half g_woh[(size_t)CDIM * HDIM];       // W_out^T fp16 [N,K]
__device__ float  g_part[BDIM * NCH * HDIM];        // cumsum partials

// ---------------------------------------------------------------------------
// PTX helpers (plain sm_80-era features only: compile under compute_103)
// ---------------------------------------------------------------------------
__device__ __forceinline__ void cpasync16(uint32_t saddr, const void* g) {
    asm volatile("cp.async.cg.shared.global [%0], [%1], 16;" :: "r"(saddr), "l"(g));
}
__device__ __forceinline__ void ldsm4(uint32_t* r, uint32_t saddr) {
    asm volatile("ldmatrix.sync.aligned.m8n8.x4.shared.b16 {%0,%1,%2,%3}, [%4];"
                 : "=r"(r[0]), "=r"(r[1]), "=r"(r[2]), "=r"(r[3]) : "r"(saddr));
}
__device__ __forceinline__ void mma_f16(float* c, const uint32_t* a,
                                        uint32_t b0, uint32_t b1) {
    asm volatile(
        "mma.sync.aligned.m16n8k16.row.col.f32.f16.f16.f32 "
        "{%0,%1,%2,%3}, {%4,%5,%6,%7}, {%8,%9}, {%0,%1,%2,%3};"
        : "+f"(c[0]), "+f"(c[1]), "+f"(c[2]), "+f"(c[3])
        : "r"(a[0]), "r"(a[1]), "r"(a[2]), "r"(a[3]), "r"(b0), "r"(b1));
}

// ---------------------------------------------------------------------------
// fp16 tensor-core GEMM: C[M,N] = A[M,K](fp16) @ Wt[N,K](fp16)^T.
// 128x128 CTA tile, 128 threads = 4 warps (2x2), FAT 64x64 warp tile:
// per ks-step 8 ldsm feed 32 HMMA (0.25 ldsm/HMMA vs 0.375 before).
// BK=64 halves, 3-stage cp.async ring, multistage schedule, 2 CTAs/SM.
// EPI: 0 = y*scale[n] ; 1 = silu(y*scale[n]) ; 2 = plain.  TO: float | __half
// ---------------------------------------------------------------------------
constexpr int BM = 128, BN = 128, BKH = 64;
constexpr int KPAD = 72;                       // halves per padded row
constexpr int ROWB = KPAD * 2;                 // 144 bytes per row
constexpr int ATILE_B = BM * ROWB;             // 18432 bytes
constexpr int STAGE_B = 2 * ATILE_B;           // A + B per stage (36864)
constexpr int STAGES = 3;
constexpr int SMEM_BYTES = STAGES * STAGE_B;   // 110592 (2 CTAs: 221K < 227K)

template <int EPI, typename TO>
__global__ __launch_bounds__(128, 2)
void hgemm(const __half* __restrict__ A, const __half* __restrict__ Wt,
           TO* __restrict__ C, const float* __restrict__ scale,
           int M, int N, int K)
{
    extern __shared__ __half sm[];
    const uint32_t smb = (uint32_t)__cvta_generic_to_shared(sm);

    const int tid  = threadIdx.x;
    const int lane = tid & 31;
    const int wid  = tid >> 5;            // 0..3
    const int wm   = (wid >> 1) * 64;     // warp m offset (0,64)
    const int wn   = (wid & 1) * 64;      // warp n offset (0,64)
    const int bm   = blockIdx.y * BM;
    const int bn   = blockIdx.x * BN;
    const int nt   = K / BKH;

    // A ldmatrix.x4 lane offset: row = lane%16, kcol = (lane/16)*8 halves
    const uint32_t a_lane = (uint32_t)((lane & 15) * ROWB + (lane >> 4) * 16);
    // B ldmatrix.x4 lane offset
    const int bg = lane >> 3, br = lane & 7;
    const uint32_t b_lane = (uint32_t)(((bg >> 1) * 8 + br) * ROWB + (bg & 1) * 16);

    auto issue_tile = [&](int t, int s) {
        const int k0 = t * BKH;
        const uint32_t ab = smb + (uint32_t)s * STAGE_B;
        const uint32_t bb = ab + ATILE_B;
        // A: 128 rows x 8 chunks = 1024 / 128 thr = 8 iters; B likewise.
#pragma unroll
        for (int i = 0; i < 8; ++i) {
            int idx = tid + (i << 7);
            int r = idx >> 3, c = idx & 7;
            uint32_t dst = (uint32_t)(r * ROWB + c * 16);
            cpasync16(ab + dst, A  + (size_t)(bm + r) * K + k0 + c * 8);
            cpasync16(bb + dst, Wt + (size_t)(bn + r) * K + k0 + c * 8);
        }
    };

    // Prologue: tiles 0 and 1 in flight; wait for tile 0.
    issue_tile(0, 0);
    asm volatile("cp.async.commit_group;");
    issue_tile(1, 1);
    asm volatile("cp.async.commit_group;");
    asm volatile("cp.async.wait_group 1;");
    __syncthreads();

    float acc[4][8][4];
#pragma unroll
    for (int i = 0; i < 4; ++i)
#pragma unroll
        for (int j = 0; j < 8; ++j)
#pragma unroll
            for (int q = 0; q < 4; ++q) acc[i][j][q] = 0.f;

    for (int t = 0; t < nt; ++t) {
        const int buf = t % STAGES;
        if (t + 2 < nt) issue_tile(t + 2, (t + 2) % STAGES);
        asm volatile("cp.async.commit_group;");

        const uint32_t ab = smb + (uint32_t)buf * STAGE_B;
        const uint32_t bb = ab + ATILE_B;
#pragma unroll
        for (int ks = 0; ks < 4; ++ks) {         // 4 x k16
            uint32_t af[4][4];
#pragma unroll
            for (int i = 0; i < 4; ++i)
                ldsm4(af[i], ab + (uint32_t)((wm + i * 16) * ROWB + ks * 32) + a_lane);
            uint32_t bf[4][4];
#pragma unroll
            for (int jj = 0; jj < 4; ++jj)
                ldsm4(bf[jj], bb + (uint32_t)((wn + jj * 16) * ROWB + ks * 32) + b_lane);
#pragma unroll
            for (int i = 0; i < 4; ++i) {
#pragma unroll
                for (int jj = 0; jj < 4; ++jj) {
                    mma_f16(acc[i][2 * jj],     af[i], bf[jj][0], bf[jj][1]);
                    mma_f16(acc[i][2 * jj + 1], af[i], bf[jj][2], bf[jj][3]);
                }
            }
        }

        asm volatile("cp.async.wait_group 1;");
        __syncthreads();
    }

    // Epilogue: direct fragment stores
    const int qr = lane >> 2;              // 0..7
    const int qc = (lane & 3) << 1;        // 0,2,4,6
#pragma unroll
    for (int i = 0; i < 4; ++i) {
        const int m0 = bm + wm + i * 16 + qr;
#pragma unroll
        for (int j = 0; j < 8; ++j) {
            const int n0 = bn + wn + j * 8 + qc;
            float v0 = acc[i][j][0], v1 = acc[i][j][1];
            float v2 = acc[i][j][2], v3 = acc[i][j][3];
            if (EPI == 0 || EPI == 1) {
                float s0 = scale[n0], s1 = scale[n0 + 1];
                v0 *= s0; v1 *= s1; v2 *= s0; v3 *= s1;
            }
            if (EPI == 1) {
                v0 = v0 / (1.f + __expf(-v0));
                v1 = v1 / (1.f + __expf(-v1));
                v2 = v2 / (1.f + __expf(-v2));
                v3 = v3 / (1.f + __expf(-v3));
            }
            if (sizeof(TO) == 2) {   // fp16 output: packed 4B stores
                __half2 p0 = __floats2half2_rn(v0, v1);
                __half2 p1 = __floats2half2_rn(v2, v3);
                *(__half2*)((__half*)C + (size_t)m0 * N + n0)       = p0;
                *(__half2*)((__half*)C + (size_t)(m0 + 8) * N + n0) = p1;
            } else {
                *(float2*)((float*)C + (size_t)m0 * N + n0)       = make_float2(v0, v1);
                *(float2*)((float*)C + (size_t)(m0 + 8) * N + n0) = make_float2(v2, v3);
            }
        }
    }
}

// ---------------------------------------------------------------------------
// Preprocessing: fp32 -> fp16 convert; all three weight transposes in one
// launch (flat tile index -> matrix select).
// ---------------------------------------------------------------------------
__global__ void cvt_half(const float4* __restrict__ in, __half2* __restrict__ out,
                         int n4)
{
    int i = blockIdx.x * blockDim.x + threadIdx.x;
    if (i < n4) {
        float4 v = in[i];
        out[2 * i]     = __floats2half2_rn(v.x, v.y);
        out[2 * i + 1] = __floats2half2_rn(v.z, v.w);
    }
}

constexpr int TSEL = (HDIM / 32) * (CDIM / 32);        // 2048
constexpr int TAGG = (2 * HDIM / 32) * (CDIM / 32);    // 4096
constexpr int TOUT = (CDIM / 32) * (HDIM / 32);        // 2048
__global__ void transpose_all(const float* __restrict__ Wsel,
                              const float* __restrict__ Wagg,
                              const float* __restrict__ Wout,
                              __half* __restrict__ wsh,
                              __half* __restrict__ wah,
                              __half* __restrict__ woh)
{
    __shared__ float t[32][33];
    int bidx = blockIdx.x;
    const float* in; __half* out; int K, N;
    if (bidx < TSEL)              { in = Wsel; out = wsh; K = CDIM; N = HDIM; }
    else if (bidx < TSEL + TAGG)  { in = Wagg; out = wah; K = CDIM; N = 2 * HDIM; bidx -= TSEL; }
    else                          { in = Wout; out = woh; K = HDIM; N = CDIM; bidx -= TSEL + TAGG; }
    const int n0 = (bidx % (N / 32)) * 32;
    const int k0 = (bidx / (N / 32)) * 32;
    const int x = threadIdx.x, y = threadIdx.y;
#pragma unroll
    for (int j = 0; j < 32; j += 8)
        t[y + j][x] = in[(size_t)(k0 + y + j) * N + n0 + x];
    __syncthreads();
#pragma unroll
    for (int j = 0; j < 32; j += 8)
        out[(size_t)(n0 + y + j) * K + k0 + x] = __float2half_rn(t[x][y + j]);
}

// ---------------------------------------------------------------------------
// Cumsum (2-phase, half2-vectorized): poly = c0 + c0*c1.
// Phase 1: per-chunk partial sums. Phase 2: scan + causal mean + gate
//   sh = half(s * acc/(t+1))   (fp16 input for GEMM3)
// ---------------------------------------------------------------------------
__global__ void poly_partial(const __half2* __restrict__ h2,
                             float2* __restrict__ part2)
{
    const int ch2 = blockIdx.x * blockDim.x + threadIdx.x;   // 0..HDIM/2-1
    const int c  = blockIdx.y, b = blockIdx.z;
    const __half2* hp = h2 + ((size_t)b * TDIM + (size_t)c * CLEN) * HDIM + ch2;
    float2 acc = make_float2(0.f, 0.f);
#pragma unroll 4
    for (int t = 0; t < CLEN; ++t) {
        float2 c0 = __half22float2(hp[(size_t)t * HDIM]);
        float2 c1 = __half22float2(hp[(size_t)t * HDIM + HDIM / 2]);
        acc.x += fmaf(c0.x, c1.x, c0.x);
        acc.y += fmaf(c0.y, c1.y, c0.y);
    }
    part2[((size_t)b * NCH + c) * (HDIM / 2) + ch2] = acc;
}
__global__ void poly_scan_gate(const __half2* __restrict__ h2,
                               const float2* __restrict__ part2,
                               const float2* __restrict__ s2,
                               __half2* __restrict__ sh2)
{
    const int ch2 = blockIdx.x * blockDim.x + threadIdx.x;
    const int c  = blockIdx.y, b = blockIdx.z;
    float2 acc = make_float2(0.f, 0.f);
    for (int c2 = 0; c2 < c; ++c2) {
        float2 p = part2[((size_t)b * NCH + c2) * (HDIM / 2) + ch2];
        acc.x += p.x; acc.y += p.y;
    }
    const __half2* hp = h2 + ((size_t)b * TDIM + (size_t)c * CLEN) * HDIM + ch2;
    const float2* sp = s2 + ((size_t)b * TDIM + (size_t)c * CLEN) * (HDIM / 2) + ch2;
    __half2* op = sh2 + ((size_t)b * TDIM + (size_t)c * CLEN) * (HDIM / 2) + ch2;
    const int t0 = c * CLEN;
#pragma unroll 4
    for (int t = 0; t < CLEN; ++t) {
        float2 c0 = __half22float2(hp[(size_t)t * HDIM]);
        float2 c1 = __half22float2(hp[(size_t)t * HDIM + HDIM / 2]);
        acc.x += fmaf(c0.x, c1.x, c0.x);
        acc.y += fmaf(c0.y, c1.y, c0.y);
        float inv = 1.0f / (float)(t0 + t + 1);
        float2 sv = sp[(size_t)t * (HDIM / 2)];
        op[(size_t)t * (HDIM / 2)] =
            __floats2half2_rn(sv.x * acc.x * inv, sv.y * acc.y * inv);
    }
}

// ---------------------------------------------------------------------------
// Launch
// ---------------------------------------------------------------------------
extern "C" void kernel_launch(void* const* d_in, const int* in_sizes, int n_in,
                              void* d_out, int out_size)
{
    const float* x     = (const float*)d_in[0];
    const float* W_sel = (const float*)d_in[1];
    const float* W_agg = (const float*)d_in[2];
    const float* W_out = (const float*)d_in[3];
    const float* sqk_q = (const float*)d_in[4];
    const float* sqk_k = (const float*)d_in[5];
    float* out = (float*)d_out;

    float *s_p, *part;
    __half *hh, *sh, *xh, *wsh, *wah, *woh;
    cudaGetSymbolAddress((void**)&s_p, g_s);
    cudaGetSymbolAddress((void**)&hh, g_hh);
    cudaGetSymbolAddress((void**)&sh, g_sh);
    cudaGetSymbolAddress((void**)&xh, g_xh);
    cudaGetSymbolAddress((void**)&wsh, g_wsh);
    cudaGetSymbolAddress((void**)&wah, g_wah);
    cudaGetSymbolAddress((void**)&woh, g_woh);
    cudaGetSymbolAddress((void**)&part, g_part);

    cudaFuncSetAttribute((const void*)hgemm<1, float>,
                         cudaFuncAttributeMaxDynamicSharedMemorySize, SMEM_BYTES);
    cudaFuncSetAttribute((const void*)hgemm<0, __half>,
                         cudaFuncAttributeMaxDynamicSharedMemorySize, SMEM_BYTES);
    cudaFuncSetAttribute((const void*)hgemm<2, float>,
                         cudaFuncAttributeMaxDynamicSharedMemorySize, SMEM_BYTES);

    // Preprocess: x -> fp16 ; weights -> transposed fp16 [N,K] (one launch)
    {
        int n4 = MTOT * CDIM / 4;
        cvt_half<<<(n4 + 255) / 256, 256>>>((const float4*)x, (__half2*)xh, n4);
        transpose_all<<<TSEL + TAGG + TOUT, dim3(32, 8)>>>(
            W_sel, W_agg, W_out, wsh, wah, woh);
    }

    dim3 blk(128);
    // s = silu((x @ W_sel) * sqk_q)            [16384 x 2048, K=1024] -> fp32
    hgemm<1, float><<<dim3(HDIM / BN, MTOT / BM), blk, SMEM_BYTES>>>(
        xh, wsh, s_p, sqk_q, MTOT, HDIM, CDIM);
    // h = (x @ W_agg) * sqk_k                  [16384 x 4096, K=1024] -> fp16
    hgemm<0, __half><<<dim3(2 * HDIM / BN, MTOT / BM), blk, SMEM_BYTES>>>(
        xh, wah, hh, sqk_k, MTOT, 2 * HDIM, CDIM);
    // poly -> causal running mean -> gate      (fp32 math, fp16 out)
    poly_partial<<<dim3(HDIM / 2 / 256, NCH, BDIM), 256>>>(
        (const __half2*)hh, (float2*)part);
    poly_scan_gate<<<dim3(HDIM / 2 / 256, NCH, BDIM), 256>>>(
        (const __half2*)hh, (const float2*)part, (const float2*)s_p, (__half2*)sh);
    // out = (s*agg) @ W_out                    [16384 x 1024, K=2048] -> fp32
    hgemm<2, float><<<dim3(CDIM / BN, MTOT / BM), blk, SMEM_BYTES>>>(
        sh, woh, out, nullptr, MTOT, CDIM, HDIM);
}